// round 12
// baseline (speedup 1.0000x reference)
#include <cuda_runtime.h>

// TemporalPSPGate: state_t = ALPHA*state_{t-1} + x_t ; out_t = x_t * sigmoid(state_t)
// x [T=16, B=16, H=8, N=256, D=64] fp32. 256 MiB logical traffic per launch.
// R5:  2048x256, depth-2 prefetch, single-MUFU tanh sigmoid.
// R10: st.global.wt stores (out never dirty in L2 -> clean replay boundary);
//      best ncu kernel 36.2us, DRAM 74.1%.
// R11: evict_last load policy proven inert across 2 rounds (x can't survive in
//      L2 vs the write stream) -> removed (pure overhead). Depth-3 prefetch:
//      MLP 2->3/thread. R0 vs R5 already showed MLP beats occupancy here
//      (MLP1@78%occ=41.9us vs MLP2@64%occ=38.1us); accept 6->5 CTAs/SM.

#define TT 16
#define SPATIAL4 ((16 * 8 * 256 * 64) / 4)   // 524,288 float4 lanes

__device__ __forceinline__ float tanh_approx(float s) {
    float r;
    asm("tanh.approx.f32 %0, %1;" : "=f"(r) : "f"(s));
    return r;
}

__device__ __forceinline__ void stg_wt(float4* p, float4 v) {
    asm volatile("st.global.wt.v4.f32 [%0], {%1,%2,%3,%4};"
                 :: "l"(p), "f"(v.x), "f"(v.y), "f"(v.z), "f"(v.w)
                 : "memory");
}

__global__ __launch_bounds__(256) void psp_gate_kernel(
    const float4* __restrict__ x, float4* __restrict__ out)
{
    const int gid = blockIdx.x * blockDim.x + threadIdx.x;
    const float alpha = 0.60653065971263342360f;   // exp(-1/2)

    const float4* xp = x + gid;
    float4*       op = out + gid;

    float4 st = make_float4(0.f, 0.f, 0.f, 0.f);

    // Depth-3 rotating prefetch: always 3 independent LDG.128 in flight.
    float4 buf0 = __ldcs(xp);
    float4 buf1 = __ldcs(xp + SPATIAL4);
    float4 buf2 = __ldcs(xp + 2 * SPATIAL4);
    xp += 3 * (long long)SPATIAL4;

    #pragma unroll
    for (int t = 0; t < TT; t++) {
        const int slot = t % 3;
        float4 xv = (slot == 0) ? buf0 : (slot == 1) ? buf1 : buf2;

        if (t + 3 < TT) {
            float4 nv = __ldcs(xp);
            if (slot == 0)      buf0 = nv;
            else if (slot == 1) buf1 = nv;
            else                buf2 = nv;
            xp += SPATIAL4;
        }

        st.x = fmaf(alpha, st.x, xv.x);
        st.y = fmaf(alpha, st.y, xv.y);
        st.z = fmaf(alpha, st.z, xv.z);
        st.w = fmaf(alpha, st.w, xv.w);

        // sigmoid(s) = 0.5*tanh(0.5*s) + 0.5 ; out = x*sigmoid
        float hx = 0.5f * xv.x;
        float hy = 0.5f * xv.y;
        float hz = 0.5f * xv.z;
        float hw = 0.5f * xv.w;

        float4 ov;
        ov.x = fmaf(hx, tanh_approx(0.5f * st.x), hx);
        ov.y = fmaf(hy, tanh_approx(0.5f * st.y), hy);
        ov.z = fmaf(hz, tanh_approx(0.5f * st.z), hz);
        ov.w = fmaf(hw, tanh_approx(0.5f * st.w), hw);

        stg_wt(op, ov);    // write-through: no dirty L2 lines at replay boundary
        op += SPATIAL4;
    }
}

extern "C" void kernel_launch(void* const* d_in, const int* in_sizes, int n_in,
                              void* d_out, int out_size) {
    const float4* x = (const float4*)d_in[0];
    float4* out = (float4*)d_out;
    const int threads = 256;
    const int blocks = SPATIAL4 / threads;   // 2048
    psp_gate_kernel<<<blocks, threads>>>(x, out);
}